// round 8
// baseline (speedup 1.0000x reference)
#include <cuda_runtime.h>
#include <math.h>
#include <stdint.h>

#define NROWS 65536
#define DDIM  64
#define KCODES 512
#define COMMIT 0.25f
#define CROWS 64             // rows per CTA (= threads per CTA)
#define KCH   128            // codes per smem chunk

// ---------------- scratch (no allocations allowed) ----------------
__device__ float  g_wnorm[KCODES];           // 0.5 * ||w_k||^2
__device__ float  g_wT[KCODES * DDIM];       // w transposed: [k][d]
__device__ int    g_counts[KCODES];
__device__ double g_sumsq;

// ---------------- packed f32x2 helpers ----------------
__device__ __forceinline__ void ffma2(unsigned long long& d,
                                      unsigned long long a,
                                      unsigned long long b) {
    asm("fma.rn.f32x2 %0, %1, %2, %0;" : "+l"(d) : "l"(a), "l"(b));
}
__device__ __forceinline__ void padd2(unsigned long long& d, unsigned long long a) {
    asm("add.rn.f32x2 %0, %0, %1;" : "+l"(d) : "l"(a));
}
__device__ __forceinline__ unsigned long long pk2(float lo, float hi) {
    unsigned long long r;
    asm("mov.b64 %0, {%1, %2};" : "=l"(r) : "f"(lo), "f"(hi));
    return r;
}
__device__ __forceinline__ void upk2(unsigned long long v, float& lo, float& hi) {
    asm("mov.b64 {%0, %1}, %2;" : "=f"(lo), "=f"(hi) : "l"(v));
}

// ---------------- kernel 0: parallel prep (wnorm + wT) ----------------
__global__ void vq_prep_kernel(const float* __restrict__ w) {
    __shared__ float tile[64][65];
    __shared__ float part[4][64];
    const int tid = threadIdx.x, b = blockIdx.x;     // 8 blocks x 256 thr
    const int k0 = b * 64;
    #pragma unroll
    for (int i = tid; i < 64 * 64; i += 256) {       // coalesced read of w
        int d = i >> 6, kl = i & 63;
        tile[kl][d] = w[d * KCODES + k0 + kl];
    }
    __syncthreads();
    {   // wnorm partials
        int kl = tid & 63, g = tid >> 6;
        float s = 0.f;
        #pragma unroll
        for (int d = g * 16; d < g * 16 + 16; d++) { float v = tile[kl][d]; s += v * v; }
        part[g][kl] = s;
    }
    __syncthreads();
    if (tid < 64)
        g_wnorm[k0 + tid] = 0.5f * (part[0][tid] + part[1][tid] + part[2][tid] + part[3][tid]);
    #pragma unroll
    for (int i = tid; i < 64 * 64; i += 256) {       // coalesced wT write
        int kl = i >> 6, d = i & 63;
        g_wT[(k0 + kl) * DDIM + d] = tile[kl][d];
    }
    if (b == 0) {
        for (int i = tid; i < KCODES; i += 256) g_counts[i] = 0;
        if (tid == 0) g_sumsq = 0.0;
    }
}

// ---------------- kernel 1: row-per-thread argmax via broadcast W ----------
// 1024 CTAs x 64 threads. Thread owns one row: 64 x-values as 32 packed
// f32x2 registers (resident all kernel). W codes broadcast from smem
// (LDS.128 same-address across the warp = conflict-free). 32 FFMA2 per
// (row, code); 4 independent accumulators for ILP.
__global__ __launch_bounds__(CROWS, 6) void vq_main_kernel(
    const float* __restrict__ x, float* __restrict__ out, int out_size)
{
    __shared__ float wbuf[KCH * DDIM];   // 32 KB: one chunk of wT rows
    __shared__ float swn[KCODES];        // 2 KB
    __shared__ int   sk[CROWS];

    const int tid  = threadIdx.x;
    const int row0 = blockIdx.x * CROWS;
    const int row  = row0 + tid;

    // load this thread's row into packed registers
    unsigned long long xp[32];
    {
        const float4* xr = (const float4*)(x + (long long)row * DDIM);
        #pragma unroll
        for (int i = 0; i < 16; i++) {
            float4 v = xr[i];
            xp[2 * i]     = pk2(v.x, v.y);
            xp[2 * i + 1] = pk2(v.z, v.w);
        }
    }
    for (int i = tid; i < KCODES; i += CROWS) swn[i] = g_wnorm[i];

    float bestv = -INFINITY;
    int   bestk = 0;

    for (int c = 0; c < 4; c++) {
        __syncthreads();
        // fill chunk: 128 codes x 64 d, coalesced from L2-hot g_wT
        {
            const float4* src = (const float4*)(g_wT + c * KCH * DDIM);
            float4* dst = (float4*)wbuf;
            #pragma unroll
            for (int i = tid; i < KCH * DDIM / 4; i += CROWS) dst[i] = src[i];
        }
        __syncthreads();

        #pragma unroll 2
        for (int kl = 0; kl < KCH; kl++) {
            const ulonglong2* wr = (const ulonglong2*)(wbuf + kl * DDIM);
            unsigned long long a0 = 0, a1 = 0, a2 = 0, a3 = 0;
            #pragma unroll
            for (int i = 0; i < 16; i += 2) {
                ulonglong2 wv0 = wr[i];       // broadcast: same addr across warp
                ulonglong2 wv1 = wr[i + 1];
                ffma2(a0, xp[2 * i],     wv0.x);
                ffma2(a1, xp[2 * i + 1], wv0.y);
                ffma2(a2, xp[2 * i + 2], wv1.x);
                ffma2(a3, xp[2 * i + 3], wv1.y);
            }
            padd2(a0, a2);
            padd2(a1, a3);
            padd2(a0, a1);
            float lo, hi;
            upk2(a0, lo, hi);
            int k = c * KCH + kl;
            float s = (lo + hi) - swn[k];
            if (s > bestv) { bestv = s; bestk = k; }   // strict >: first max
        }
    }

    const long long idx_off = (long long)NROWS * DDIM + 2;
    const bool write_q   = (out_size >= (long long)NROWS * DDIM);
    const bool write_idx = (out_size >= idx_off + NROWS);

    sk[tid] = bestk;
    atomicAdd(&g_counts[bestk], 1);
    if (write_idx) out[idx_off + row] = (float)bestk;
    __syncthreads();

    // fused gather: coalesced quantized write + squared error
    float partial = 0.f;
    if (write_q) {
        const int d = tid & 63;                    // 1 row per iteration
        #pragma unroll 4
        for (int r = 0; r < CROWS; r++) {
            int k = sk[r];
            float q  = g_wT[k * DDIM + d];
            float xv = x[(long long)(row0 + r) * DDIM + d];
            out[(long long)(row0 + r) * DDIM + d] = q;   // quantized_st == quantized
            float df = q - xv;
            partial += df * df;
        }
    }
    #pragma unroll
    for (int o = 16; o > 0; o >>= 1)
        partial += __shfl_down_sync(0xFFFFFFFFu, partial, o);
    if ((tid & 31) == 0) atomicAdd(&g_sumsq, (double)partial);
}

// ---------------- kernel 2: loss + perplexity ----------------
__global__ void vq_final_kernel(float* __restrict__ out, int out_size) {
    __shared__ float red[512];
    int t = threadIdx.x;
    float p = (float)g_counts[t] * (1.0f / (float)NROWS);
    red[t] = p * logf(p + 1e-10f);
    __syncthreads();
    for (int s = 256; s > 0; s >>= 1) {
        if (t < s) red[t] += red[t + s];
        __syncthreads();
    }
    if (t == 0) {
        long long base = (long long)NROWS * DDIM;
        if (out_size >= base + 2) {
            double mse = g_sumsq / (double)((long long)NROWS * DDIM);
            out[base]     = (float)((1.0 + (double)COMMIT) * mse);  // q + 0.25*e
            out[base + 1] = expf(-red[0]);
        }
    }
}

// ---------------- launch ----------------
extern "C" void kernel_launch(void* const* d_in, const int* in_sizes, int n_in,
                              void* d_out, int out_size) {
    const float* x = (const float*)d_in[0];   // [65536, 64]
    const float* w = (const float*)d_in[1];   // [64, 512]
    float* out = (float*)d_out;

    vq_prep_kernel<<<8, 256>>>(w);
    vq_main_kernel<<<NROWS / CROWS, CROWS>>>(x, out, out_size);
    vq_final_kernel<<<1, 512>>>(out, out_size);
}

// round 15
// speedup vs baseline: 1.8232x; 1.8232x over previous
#include <cuda_runtime.h>
#include <cuda_fp16.h>
#include <math.h>
#include <stdint.h>

#define NROWS 65536
#define DDIM  64
#define KCODES 512
#define COMMIT 0.25f
#define CROWS 64             // rows per CTA (4 warps x 16)
#define KCH   128            // codes per smem chunk

// ---------------- scratch (no allocations allowed) ----------------
__device__ float    g_wnorm[KCODES];            // 0.5*||w_k||^2
__device__ float    g_wT[KCODES * DDIM];        // w transposed [k][d] fp32
__device__ uint32_t g_whp[KCODES * DDIM / 2];   // w hi fp16, half2-packed [k][d/2]
__device__ uint32_t g_wlp[KCODES * DDIM / 2];   // w lo fp16 (residual)
__device__ int      g_counts[KCODES];
__device__ double   g_sumsq;

// ---------------- helpers ----------------
__device__ __forceinline__ unsigned int f2ord(float f) {
    unsigned int u = __float_as_uint(f);
    return (u & 0x80000000u) ? ~u : (u | 0x80000000u);
}
__device__ __forceinline__ void split16(float v, __half& hi, __half& lo) {
    hi = __float2half_rn(v);
    lo = __float2half_rn(v - __half2float(hi));
}
__device__ __forceinline__ uint32_t pkh2(__half a, __half b) {
    __half2 h = __halves2half2(a, b);
    return *(uint32_t*)&h;
}
// m16n8k16 row.col fp16 -> fp32 accumulate (legacy HMMA, portable PTX)
__device__ __forceinline__ void mma16816(float c[4], const uint32_t a[4],
                                         uint32_t b0, uint32_t b1) {
    asm("mma.sync.aligned.m16n8k16.row.col.f32.f16.f16.f32 "
        "{%0,%1,%2,%3}, {%4,%5,%6,%7}, {%8,%9}, {%0,%1,%2,%3};"
        : "+f"(c[0]), "+f"(c[1]), "+f"(c[2]), "+f"(c[3])
        : "r"(a[0]), "r"(a[1]), "r"(a[2]), "r"(a[3]), "r"(b0), "r"(b1));
}
__device__ __forceinline__ void top2upd(float& v1, int& k1, float& v2, int& k2,
                                        float s, int kk) {
    if (s > v1)      { v2 = v1; k2 = k1; v1 = s; k1 = kk; }
    else if (s > v2) { v2 = s; k2 = kk; }
}

// ---------------- kernel 0: prep (wnorm, wT, fp16 splits, zero) ------------
__global__ void vq_prep_kernel(const float* __restrict__ w) {
    __shared__ float tile[16][65];
    const int tid = threadIdx.x, k0 = blockIdx.x * 16;   // 32 blocks x 256
    for (int i = tid; i < 16 * 64; i += 256) {
        int d = i >> 4, kl = i & 15;
        tile[kl][d] = w[d * KCODES + k0 + kl];
    }
    __syncthreads();
    if (tid < 16) {
        float s = 0.f;
        #pragma unroll
        for (int d = 0; d < 64; d++) { float v = tile[tid][d]; s += v * v; }
        g_wnorm[k0 + tid] = 0.5f * s;
    }
    for (int i = tid; i < 16 * 64; i += 256) {
        int kl = i >> 6, d = i & 63;
        g_wT[(k0 + kl) * DDIM + d] = tile[kl][d];
    }
    for (int i = tid; i < 16 * 32; i += 256) {
        int kl = i >> 5, dw = i & 31;
        float f0 = tile[kl][2 * dw], f1 = tile[kl][2 * dw + 1];
        __half h0, l0, h1, l1;
        split16(f0, h0, l0);
        split16(f1, h1, l1);
        g_whp[(k0 + kl) * 32 + dw] = pkh2(h0, h1);
        g_wlp[(k0 + kl) * 32 + dw] = pkh2(l0, l1);
    }
    if (blockIdx.x == 0) {
        for (int i = tid; i < KCODES; i += 256) g_counts[i] = 0;
        if (tid == 0) g_sumsq = 0.0;
    }
}

// ---------------- smem layout (dynamic) ----------------
#define XS_PITCH 68
#define SM_XS    0                                   // 64 x 68 f32 = 17408
#define SM_WH    17408                               // 128 x 72 half = 18432
#define SM_WL    (17408 + 18432)                     // 18432
#define SM_SWN   (SM_WL + 18432)                     // 512 f32 = 2048
#define SM_SK    (SM_SWN + 2048)                     // 64 int
#define SM_MAIN  (SM_SK + 256)

// ---------------- kernel 1: HMMA 3-split scoring + argmax + gather ---------
// 1024 CTAs x 128 thr. Warp w: rows w*16..w*16+15 (m16). Codes in n8 pairs,
// 2-way interleaved accumulators; fp32 acc; top-2 tracked; exact rescore.
__global__ __launch_bounds__(128) void vq_main_kernel(
    const float* __restrict__ x, float* __restrict__ out, int out_size)
{
    extern __shared__ unsigned char smraw[];
    float*  xs  = (float*)(smraw + SM_XS);           // [64][68]
    __half* whs = (__half*)(smraw + SM_WH);          // [128][72]
    __half* wls = (__half*)(smraw + SM_WL);
    float*  swn = (float*)(smraw + SM_SWN);
    int*    sk  = (int*)(smraw + SM_SK);

    const int tid  = threadIdx.x;
    const int lane = tid & 31, warp = tid >> 5;
    const int g = lane >> 2, tg = lane & 3;
    const int row0 = blockIdx.x * CROWS;
    const int rA = warp * 16 + g, rB = rA + 8;       // this thread's 2 rows

    // x tile -> smem (coalesced)
    for (int i = tid; i < CROWS * DDIM; i += 128) {
        int r = i >> 6, d = i & 63;
        xs[r * XS_PITCH + d] = x[(long long)(row0 + r) * DDIM + d];
    }
    for (int i = tid; i < KCODES; i += 128) swn[i] = g_wnorm[i];
    __syncthreads();

    // build A fragments (4 ksteps, hi+lo splits) from xs
    uint32_t ahi[4][4], alo[4][4];
    #pragma unroll
    for (int ks = 0; ks < 4; ks++) {
        #pragma unroll
        for (int q = 0; q < 4; q++) {              // q: {rA,c0},{rB,c0},{rA,c8},{rB,c8}
            int rr = (q & 1) ? rB : rA;
            int cc = ks * 16 + 2 * tg + ((q >> 1) << 3);
            float2 v = *(float2*)&xs[rr * XS_PITCH + cc];
            __half h0, l0, h1, l1;
            split16(v.x, h0, l0);
            split16(v.y, h1, l1);
            ahi[ks][q] = pkh2(h0, h1);
            alo[ks][q] = pkh2(l0, l1);
        }
    }

    float v1a = -INFINITY, v2a = -INFINITY, v1b = -INFINITY, v2b = -INFINITY;
    int   k1a = 0, k2a = 0, k1b = 0, k2b = 0;

    for (int c = 0; c < 4; c++) {
        __syncthreads();
        // fill fp16 chunk (coalesced global, conflict-free smem)
        for (int i = tid; i < KCH * 32; i += 128) {
            int kl = i >> 5, dw = i & 31;
            *(uint32_t*)&whs[kl * 72 + dw * 2] = g_whp[(c * KCH + kl) * 32 + dw];
            *(uint32_t*)&wls[kl * 72 + dw * 2] = g_wlp[(c * KCH + kl) * 32 + dw];
        }
        __syncthreads();

        for (int g8 = 0; g8 < 8; g8++) {
            const int lc = g8 * 16;                 // chunk-local code base
            float acc0[4] = {0.f, 0.f, 0.f, 0.f};
            float acc1[4] = {0.f, 0.f, 0.f, 0.f};
            #pragma unroll
            for (int ks = 0; ks < 4; ks++) {
                const int bo = (lc + g) * 72 + ks * 16 + 2 * tg;
                uint32_t b0h = *(uint32_t*)&whs[bo];
                uint32_t b1h = *(uint32_t*)&whs[bo + 8];
                uint32_t b0h2 = *(uint32_t*)&whs[bo + 8 * 72];
                uint32_t b1h2 = *(uint32_t*)&whs[bo + 8 * 72 + 8];
                uint32_t b0l = *(uint32_t*)&wls[bo];
                uint32_t b1l = *(uint32_t*)&wls[bo + 8];
                uint32_t b0l2 = *(uint32_t*)&wls[bo + 8 * 72];
                uint32_t b1l2 = *(uint32_t*)&wls[bo + 8 * 72 + 8];
                mma16816(acc0, ahi[ks], b0h, b1h);
                mma16816(acc1, ahi[ks], b0h2, b1h2);
                mma16816(acc0, alo[ks], b0h, b1h);
                mma16816(acc1, alo[ks], b0h2, b1h2);
                mma16816(acc0, ahi[ks], b0l, b1l);
                mma16816(acc1, ahi[ks], b0l2, b1l2);
            }
            // epilogue: 2 subs x (2 rows x 2 codes)
            #pragma unroll
            for (int u = 0; u < 2; u++) {
                float* a = u ? acc1 : acc0;
                int cn = c * KCH + lc + u * 8 + 2 * tg;
                float s0 = a[0] - swn[cn];
                float s1 = a[1] - swn[cn + 1];
                float s2 = a[2] - swn[cn];
                float s3 = a[3] - swn[cn + 1];
                top2upd(v1a, k1a, v2a, k2a, s0, cn);
                top2upd(v1a, k1a, v2a, k2a, s1, cn + 1);
                top2upd(v1b, k1b, v2b, k2b, s2, cn);
                top2upd(v1b, k1b, v2b, k2b, s3, cn + 1);
            }
        }
    }

    // quad-lane top-2 merge per row (keys: ordered score | inverted idx)
    unsigned long long kA1 = ((unsigned long long)f2ord(v1a) << 32) | (unsigned)(511 - k1a);
    unsigned long long kA2 = ((unsigned long long)f2ord(v2a) << 32) | (unsigned)(511 - k2a);
    unsigned long long kB1 = ((unsigned long long)f2ord(v1b) << 32) | (unsigned)(511 - k1b);
    unsigned long long kB2 = ((unsigned long long)f2ord(v2b) << 32) | (unsigned)(511 - k2b);
    #pragma unroll
    for (int off = 1; off <= 2; off <<= 1) {
        unsigned long long oA1 = __shfl_xor_sync(0xFFFFFFFFu, kA1, off);
        unsigned long long oA2 = __shfl_xor_sync(0xFFFFFFFFu, kA2, off);
        unsigned long long oB1 = __shfl_xor_sync(0xFFFFFFFFu, kB1, off);
        unsigned long long oB2 = __shfl_xor_sync(0xFFFFFFFFu, kB2, off);
        unsigned long long n1 = kA1 > oA1 ? kA1 : oA1;
        unsigned long long m1 = kA1 > oA1 ? oA1 : kA1;
        unsigned long long n2 = kA2 > oA2 ? kA2 : oA2;
        kA1 = n1; kA2 = m1 > n2 ? m1 : n2;
        n1 = kB1 > oB1 ? kB1 : oB1;
        m1 = kB1 > oB1 ? oB1 : kB1;
        n2 = kB2 > oB2 ? kB2 : oB2;
        kB1 = n1; kB2 = m1 > n2 ? m1 : n2;
    }

    const long long idx_off = (long long)NROWS * DDIM + 2;
    const bool write_q   = (out_size >= (long long)NROWS * DDIM);
    const bool write_idx = (out_size >= idx_off + NROWS);

    // lanes tg 0/1: exact fp32 rescore of top-2, final pick
    if (tg < 2) {
        int r = tg ? rB : rA;
        unsigned long long q1 = tg ? kB1 : kA1, q2 = tg ? kB2 : kA2;
        int c1 = 511 - (int)(q1 & 0xFFFFFFFFu);
        int c2 = 511 - (int)(q2 & 0xFFFFFFFFu);
        const float4* xr = (const float4*)&xs[r * XS_PITCH];
        const float4* w1 = (const float4*)(g_wT + c1 * DDIM);
        const float4* w2 = (const float4*)(g_wT + c2 * DDIM);
        float s1 = 0.f, s2 = 0.f;
        #pragma unroll
        for (int q = 0; q < 16; q++) {
            float4 xv = xr[q], a = w1[q], b = w2[q];
            s1 += xv.x * a.x + xv.y * a.y + xv.z * a.z + xv.w * a.w;
            s2 += xv.x * b.x + xv.y * b.y + xv.z * b.z + xv.w * b.w;
        }
        s1 -= swn[c1]; s2 -= swn[c2];
        int kf = (s2 > s1 || (s2 == s1 && c2 < c1)) ? c2 : c1;
        sk[r] = kf;
        atomicAdd(&g_counts[kf], 1);
        if (write_idx) out[idx_off + row0 + r] = (float)kf;
    }
    __syncthreads();

    // fused gather: quantized out + squared error (x from smem)
    float partial = 0.f;
    if (write_q) {
        const int d = tid & 63, rh = tid >> 6;
        #pragma unroll 4
        for (int it = 0; it < CROWS / 2; it++) {
            int r = it * 2 + rh;
            int k = sk[r];
            float q  = g_wT[k * DDIM + d];
            float xv = xs[r * XS_PITCH + d];
            out[(long long)(row0 + r) * DDIM + d] = q;   // quantized_st == quantized
            float df = q - xv;
            partial += df * df;
        }
    }
    #pragma unroll
    for (int o = 16; o > 0; o >>= 1)
        partial += __shfl_down_sync(0xFFFFFFFFu, partial, o);
    if (lane == 0) atomicAdd(&g_sumsq, (double)partial);
}

// ---------------- kernel 2: loss + perplexity ----------------
__global__ void vq_final_kernel(float* __restrict__ out, int out_size) {
    __shared__ float red[512];
    int t = threadIdx.x;
    float p = (float)g_counts[t] * (1.0f / (float)NROWS);
    red[t] = p * logf(p + 1e-10f);
    __syncthreads();
    for (int s = 256; s > 0; s >>= 1) {
        if (t < s) red[t] += red[t + s];
        __syncthreads();
    }
    if (t == 0) {
        long long base = (long long)NROWS * DDIM;
        if (out_size >= base + 2) {
            double mse = g_sumsq / (double)((long long)NROWS * DDIM);
            out[base]     = (float)((1.0 + (double)COMMIT) * mse);
            out[base + 1] = expf(-red[0]);
        }
    }
}

// ---------------- launch ----------------
extern "C" void kernel_launch(void* const* d_in, const int* in_sizes, int n_in,
                              void* d_out, int out_size) {
    const float* x = (const float*)d_in[0];   // [65536, 64]
    const float* w = (const float*)d_in[1];   // [64, 512]
    float* out = (float*)d_out;

    cudaFuncSetAttribute(vq_main_kernel,
                         cudaFuncAttributeMaxDynamicSharedMemorySize, SM_MAIN);

    vq_prep_kernel<<<32, 256>>>(w);
    vq_main_kernel<<<NROWS / CROWS, 128, SM_MAIN>>>(x, out, out_size);
    vq_final_kernel<<<1, 512>>>(out, out_size);
}